// round 2
// baseline (speedup 1.0000x reference)
#include <cuda_runtime.h>
#include <cuda_bf16.h>
#include <math_constants.h>

#define DIM    128
#define HEADS  4
#define FH     32
#define LAYERS 3
#define NEG    0.2f
#define GEPS   1e-16f
#define MAXN   50000
#define MAXE   600000

// ---------------- scratch (device globals; no allocations allowed) ----------
__device__ float    g_x   [MAXN * DIM];     // layer input  (node features)
__device__ float    g_h   [MAXN * DIM];     // h = x @ W
__device__ float    g_asrc[MAXN * HEADS];
__device__ float    g_adst[MAXN * HEADS];
__device__ int      g_deg [MAXN];           // degree (incl. self loop)
__device__ int      g_rptr[MAXN + 1];       // CSR row ptr (by dst)
__device__ int      g_cur [MAXN];           // scatter cursor
__device__ int      g_csrc[MAXE + MAXN];    // src ids grouped by dst
__device__ float    g_expg[MAXN];           // exp(gate_i) for global attention
__device__ float    g_vec [2][DIM];         // pooled numerator per graph
__device__ float    g_sum [2];              // pooled denominator per graph

// ---------------- embedding gather ------------------------------------------
__global__ void k_gather(const int* __restrict__ idx,
                         const float* __restrict__ embed, int n) {
    int t = blockIdx.x * blockDim.x + threadIdx.x;
    if (t >= n * 32) return;                      // float4 granularity
    int i = t >> 5, q = t & 31;
    ((float4*)g_x)[t] = ((const float4*)embed)[idx[i] * 32 + q];
}

// ---------------- CSR build (once per graph, reused for 3 layers) -----------
__global__ void k_deg0(int n) {
    int t = blockIdx.x * blockDim.x + threadIdx.x;
    if (t < n) g_deg[t] = 1;                      // self loop
}
__global__ void k_count(const int* __restrict__ ei, int E) {
    int t = blockIdx.x * blockDim.x + threadIdx.x;
    if (t < E) atomicAdd(&g_deg[ei[E + t]], 1);
}
__global__ __launch_bounds__(1024) void k_scan(int n) {
    __shared__ int part[1024];
    int t = threadIdx.x;
    int chunk = (n + 1023) >> 10;
    int b = t * chunk, e = min(b + chunk, n);
    int sum = 0;
    for (int i = b; i < e; i++) sum += g_deg[i];
    part[t] = sum;
    __syncthreads();
    for (int off = 1; off < 1024; off <<= 1) {
        int v = (t >= off) ? part[t - off] : 0;
        __syncthreads();
        part[t] += v;
        __syncthreads();
    }
    int run = part[t] - sum;                      // exclusive prefix
    for (int i = b; i < e; i++) { g_rptr[i] = run; run += g_deg[i]; }
    if (t == 1023) g_rptr[n] = part[1023];
}
__global__ void k_fill(int n) {                   // place self loop + init cursor
    int t = blockIdx.x * blockDim.x + threadIdx.x;
    if (t >= n) return;
    int p = g_rptr[t];
    g_csrc[p] = t;
    g_cur[t] = p + 1;
}
__global__ void k_scatter(const int* __restrict__ ei, int E) {
    int t = blockIdx.x * blockDim.x + threadIdx.x;
    if (t >= E) return;
    int dst = ei[E + t];
    int pos = atomicAdd(&g_cur[dst], 1);
    g_csrc[pos] = ei[t];
}

// ---------------- h = x @ W[l]  (+ fused alpha dot-products) ----------------
// 256 threads, 64-row x 128-col tile, 4x8 register tile per thread.
extern __shared__ float s_mm[];
__global__ __launch_bounds__(256) void k_mm(const float* __restrict__ W,
                                            const float* __restrict__ att_s,
                                            const float* __restrict__ att_d,
                                            int l, int n) {
    float* Ws = s_mm;                    // [128][128]
    float* Xs = s_mm + 16384;            // [64][132] padded
    int tid = threadIdx.x;
    float4* Ws4 = (float4*)Ws;
    const float4* Wg4 = (const float4*)(W + l * DIM * DIM);
    #pragma unroll
    for (int i = 0; i < 16; i++) Ws4[tid + 256 * i] = Wg4[tid + 256 * i];

    int row0 = blockIdx.x * 64;
    #pragma unroll
    for (int i = 0; i < 8; i++) {
        int idx = tid + 256 * i;         // f4 index: row = idx>>5, k4 = idx&31
        int r = idx >> 5, k4 = idx & 31;
        float4 v = make_float4(0.f, 0.f, 0.f, 0.f);
        if (row0 + r < n) v = ((const float4*)g_x)[(row0 + r) * 32 + k4];
        float* d = Xs + r * 132 + k4 * 4;
        d[0] = v.x; d[1] = v.y; d[2] = v.z; d[3] = v.w;
    }
    __syncthreads();

    int cg = tid & 15, rg = tid >> 4;    // colgroup (8 cols), rowgroup (4 rows)
    float acc[4][8];
    #pragma unroll
    for (int i = 0; i < 4; i++)
        #pragma unroll
        for (int j = 0; j < 8; j++) acc[i][j] = 0.f;

    const float* xs0 = Xs + (rg * 4) * 132;
    #pragma unroll 4
    for (int k = 0; k < DIM; k++) {
        float4 w0 = Ws4[k * 32 + cg * 2];
        float4 w1 = Ws4[k * 32 + cg * 2 + 1];
        float wv[8] = {w0.x, w0.y, w0.z, w0.w, w1.x, w1.y, w1.z, w1.w};
        float xv[4] = {xs0[k], xs0[132 + k], xs0[264 + k], xs0[396 + k]};
        #pragma unroll
        for (int i = 0; i < 4; i++)
            #pragma unroll
            for (int j = 0; j < 8; j++)
                acc[i][j] = fmaf(xv[i], wv[j], acc[i][j]);
    }

    // alpha vectors for my 8 columns (att[l][head][f] flat = l*128 + c)
    const float4* as4 = (const float4*)(att_s + l * DIM);
    const float4* ad4 = (const float4*)(att_d + l * DIM);
    float4 A0 = as4[cg * 2], A1 = as4[cg * 2 + 1];
    float4 D0 = ad4[cg * 2], D1 = ad4[cg * 2 + 1];
    float av[8] = {A0.x, A0.y, A0.z, A0.w, A1.x, A1.y, A1.z, A1.w};
    float dv[8] = {D0.x, D0.y, D0.z, D0.w, D1.x, D1.y, D1.z, D1.w};
    int head = cg >> 2;

    #pragma unroll
    for (int i = 0; i < 4; i++) {
        int row = row0 + rg * 4 + i;
        if (row < n) {
            float4 h0 = make_float4(acc[i][0], acc[i][1], acc[i][2], acc[i][3]);
            float4 h1 = make_float4(acc[i][4], acc[i][5], acc[i][6], acc[i][7]);
            ((float4*)g_h)[row * 32 + cg * 2]     = h0;
            ((float4*)g_h)[row * 32 + cg * 2 + 1] = h1;
        }
        float ps = 0.f, pd = 0.f;
        #pragma unroll
        for (int j = 0; j < 8; j++) {
            ps = fmaf(acc[i][j], av[j], ps);
            pd = fmaf(acc[i][j], dv[j], pd);
        }
        ps += __shfl_xor_sync(0xFFFFFFFFu, ps, 1);
        ps += __shfl_xor_sync(0xFFFFFFFFu, ps, 2);
        pd += __shfl_xor_sync(0xFFFFFFFFu, pd, 1);
        pd += __shfl_xor_sync(0xFFFFFFFFu, pd, 2);
        if ((cg & 3) == 0 && row < n) {
            g_asrc[row * HEADS + head] = ps;
            g_adst[row * HEADS + head] = pd;
        }
    }
}

// ---------------- per-dst aggregation: online softmax, fused epilogue -------
// 1 warp per dst node; lane owns 4 feature dims (float4), head = lane>>3.
__device__ __forceinline__ float pick(float4 v, int h) {
    return h == 0 ? v.x : h == 1 ? v.y : h == 2 ? v.z : v.w;
}
__device__ __forceinline__ void step(float src_a, float adh, float4 hv,
                                     float& m, float& s, float4& acc) {
    float v = src_a + adh;
    v = v > 0.f ? v : NEG * v;
    float nm = fmaxf(m, v);
    float sc = __expf(m - nm);      // m=-inf first iter -> 0
    float p  = __expf(v - nm);
    s = s * sc + p;
    acc.x = fmaf(p, hv.x, acc.x * sc);
    acc.y = fmaf(p, hv.y, acc.y * sc);
    acc.z = fmaf(p, hv.z, acc.z * sc);
    acc.w = fmaf(p, hv.w, acc.w * sc);
    m = nm;
}
__global__ __launch_bounds__(256) void k_agg(const float* __restrict__ bias,
                                             int l, int n) {
    int w = (blockIdx.x * blockDim.x + threadIdx.x) >> 5;
    if (w >= n) return;
    int lane = threadIdx.x & 31;
    int head = lane >> 3;
    const float4* asrc4 = (const float4*)g_asrc;
    const float4* h4    = (const float4*)g_h;
    float adh = pick(((const float4*)g_adst)[w], head);

    int e = g_rptr[w], end = g_rptr[w + 1];
    float m = -CUDART_INF_F, s = 0.f;
    float4 acc = make_float4(0.f, 0.f, 0.f, 0.f);

    for (; e + 1 < end; e += 2) {
        int s0 = g_csrc[e], s1 = g_csrc[e + 1];
        float a0 = pick(asrc4[s0], head);
        float a1 = pick(asrc4[s1], head);
        float4 hv0 = h4[s0 * 32 + lane];
        float4 hv1 = h4[s1 * 32 + lane];
        step(a0, adh, hv0, m, s, acc);
        step(a1, adh, hv1, m, s, acc);
    }
    if (e < end) {
        int s0 = g_csrc[e];
        step(pick(asrc4[s0], head), adh, h4[s0 * 32 + lane], m, s, acc);
    }

    float inv = 1.0f / (s + GEPS);
    float4 b = ((const float4*)(bias + l * DIM))[lane];
    float4 o;
    o.x = fmaf(acc.x, inv, b.x); o.x = o.x > 0.f ? o.x : 0.f;
    o.y = fmaf(acc.y, inv, b.y); o.y = o.y > 0.f ? o.y : 0.f;
    o.z = fmaf(acc.z, inv, b.z); o.z = o.z > 0.f ? o.z : 0.f;
    o.w = fmaf(acc.w, inv, b.w); o.w = o.w > 0.f ? o.w : 0.f;
    ((float4*)g_x)[w * 32 + lane] = o;
}

// ---------------- global attention pooling ----------------------------------
__global__ void k_ginit(int gi) {
    if (threadIdx.x == 0) g_sum[gi] = 0.0f;
    if (threadIdx.x < DIM) g_vec[gi][threadIdx.x] = 0.0f;
}
__global__ __launch_bounds__(256) void k_gate1(const float* __restrict__ gw,
                                               const float* __restrict__ gb,
                                               int n, int gi) {
    int w = (blockIdx.x * blockDim.x + threadIdx.x) >> 5;
    int lane = threadIdx.x & 31;
    if (w >= n) return;
    float4 xr = ((const float4*)g_x)[w * 32 + lane];
    float4 gv = ((const float4*)gw)[lane];
    float acc = xr.x * gv.x + xr.y * gv.y + xr.z * gv.z + xr.w * gv.w;
    #pragma unroll
    for (int o = 16; o; o >>= 1) acc += __shfl_xor_sync(0xFFFFFFFFu, acc, o);
    if (lane == 0) {
        float g  = 1.0f / (1.0f + __expf(-(acc + gb[0])));
        float eg = __expf(g);           // softmax shift-invariant; g in (0,1)
        g_expg[w] = eg;
        atomicAdd(&g_sum[gi], eg);
    }
}
__global__ __launch_bounds__(128) void k_gate2(int n, int gi) {
    int d = threadIdx.x;
    float acc = 0.0f;
    for (int i = blockIdx.x; i < n; i += gridDim.x)
        acc = fmaf(g_expg[i], g_x[i * DIM + d], acc);
    atomicAdd(&g_vec[gi][d], acc);
}

// ---------------- head MLP ---------------------------------------------------
__global__ __launch_bounds__(128) void k_final(const float* __restrict__ fc1w,
                                               const float* __restrict__ fc1b,
                                               const float* __restrict__ fc2w,
                                               const float* __restrict__ fc2b,
                                               float* __restrict__ out) {
    __shared__ float gcat[2 * DIM];
    __shared__ float hid[DIM];
    int t = threadIdx.x;
    gcat[t]       = g_vec[0][t] / g_sum[0];
    gcat[DIM + t] = g_vec[1][t] / g_sum[1];
    __syncthreads();
    float acc = fc1b[t];
    #pragma unroll 8
    for (int k = 0; k < 2 * DIM; k++) acc = fmaf(gcat[k], fc1w[k * DIM + t], acc);
    acc = acc > 0.0f ? acc : 0.0f;
    hid[t] = acc * fc2w[t];
    __syncthreads();
    for (int s = 64; s; s >>= 1) {
        if (t < s) hid[t] += hid[t + s];
        __syncthreads();
    }
    if (t == 0) out[0] = hid[0] + fc2b[0];
}

// ---------------- launch ----------------------------------------------------
extern "C" void kernel_launch(void* const* d_in, const int* in_sizes, int n_in,
                              void* d_out, int out_size) {
    const int*   x1      = (const int*)  d_in[0];
    const int*   x2      = (const int*)  d_in[1];
    const int*   ei1     = (const int*)  d_in[2];
    const int*   ei2     = (const int*)  d_in[3];
    const float* embed   = (const float*)d_in[4];
    const float* W       = (const float*)d_in[5];
    const float* att_src = (const float*)d_in[6];
    const float* att_dst = (const float*)d_in[7];
    const float* bias    = (const float*)d_in[8];
    const float* gate_w  = (const float*)d_in[9];
    const float* gate_b  = (const float*)d_in[10];
    const float* fc1_w   = (const float*)d_in[11];
    const float* fc1_b   = (const float*)d_in[12];
    const float* fc2_w   = (const float*)d_in[13];
    const float* fc2_b   = (const float*)d_in[14];
    float* out = (float*)d_out;

    int n = in_sizes[0];
    int E = in_sizes[2] / 2;

    static int smem_set = -1;
    int smem_mm = (16384 + 64 * 132) * 4;         // 97.0 KB
    cudaFuncSetAttribute(k_mm, cudaFuncAttributeMaxDynamicSharedMemorySize,
                         smem_mm);
    (void)smem_set;

    int gN256 = (n + 255) / 256;
    int gE256 = (E + 255) / 256;
    int gGath = (n * 32 + 255) / 256;
    int gMM   = (n + 63) / 64;
    int gAgg  = (n * 32 + 255) / 256;             // 1 warp per node
    int gGate = (n * 32 + 255) / 256;

    for (int gi = 0; gi < 2; gi++) {
        const int* idx = gi ? x2  : x1;
        const int* ei  = gi ? ei2 : ei1;

        k_gather <<<gGath, 256>>>(idx, embed, n);
        // CSR by dst (amortized over the 3 layers)
        k_deg0   <<<gN256, 256>>>(n);
        k_count  <<<gE256, 256>>>(ei, E);
        k_scan   <<<1, 1024>>>(n);
        k_fill   <<<gN256, 256>>>(n);
        k_scatter<<<gE256, 256>>>(ei, E);

        for (int l = 0; l < LAYERS; l++) {
            k_mm <<<gMM, 256, smem_mm>>>(W, att_src, att_dst, l, n);
            k_agg<<<gAgg, 256>>>(bias, l, n);
        }
        k_ginit<<<1, 128>>>(gi);
        k_gate1<<<gGate, 256>>>(gate_w, gate_b, n, gi);
        k_gate2<<<256, 128>>>(n, gi);
    }
    k_final<<<1, 128>>>(fc1_w, fc1_b, fc2_w, fc2_b, out);
}

// round 7
// speedup vs baseline: 1.6616x; 1.6616x over previous
#include <cuda_runtime.h>
#include <cuda_bf16.h>
#include <math_constants.h>

#define DIM    128
#define HEADS  4
#define FH     32
#define LAYERS 3
#define NEG    0.2f
#define GEPS   1e-16f
#define MAXN   50000
#define MAXE   600000
#define MAXN2  (2 * MAXN)            // both graphs fused
#define MAXEL  (2 * (MAXE + MAXN))   // edges + self loops, both graphs

// ---------------- scratch (device globals; no allocations allowed) ----------
__device__ float    g_x   [MAXN2 * DIM];     // layer input  (node features)
__device__ float    g_h   [MAXN2 * DIM];     // h = x @ W
__device__ float    g_asrc[MAXN2 * HEADS];
__device__ float    g_adst[MAXN2 * HEADS];
__device__ int      g_deg [MAXN2];           // degree (incl. self loop)
__device__ int      g_rptr[MAXN2 + 1];       // CSR row ptr (by dst)
__device__ int      g_cur [MAXN2];           // scatter cursor
__device__ int      g_csrc[MAXEL];           // src ids grouped by dst
__device__ int      g_bsum[256];             // scan partials
__device__ int      g_boff[256];             // scan block offsets
__device__ float    g_expg[MAXN2];           // exp(gate_i) for global attention
__device__ float    g_vec [2][DIM];          // pooled numerator per graph
__device__ float    g_sum [2];               // pooled denominator per graph

// ---------------- embedding gather (+ degree init), both graphs --------------
__global__ void k_gather(const int* __restrict__ x1, const int* __restrict__ x2,
                         const float* __restrict__ embed, int n) {
    int t = blockIdx.x * blockDim.x + threadIdx.x;
    int n2 = 2 * n;
    if (t < n2) g_deg[t] = 1;                     // self loop
    if (t >= n2 * 32) return;                     // float4 granularity
    int i = t >> 5, q = t & 31;
    int v = (i < n) ? x1[i] : x2[i - n];
    ((float4*)g_x)[t] = ((const float4*)embed)[v * 32 + q];
}

// ---------------- CSR build (once, reused for 3 layers) ----------------------
__global__ void k_count(const int* __restrict__ ei1, const int* __restrict__ ei2,
                        int E, int n) {
    int t = blockIdx.x * blockDim.x + threadIdx.x;
    if (t >= 2 * E) return;
    int dst = (t < E) ? ei1[E + t] : (ei2[E + (t - E)] + n);
    atomicAdd(&g_deg[dst], 1);
}

// block-local exclusive scan of degrees (512/block), partial sums to g_bsum
__global__ __launch_bounds__(512) void k_s1(int n2) {
    __shared__ int wsum[16];
    int t = threadIdx.x, g = blockIdx.x * 512 + t;
    int lane = t & 31, wid = t >> 5;
    int v = (g < n2) ? g_deg[g] : 0;
    int x = v;
    #pragma unroll
    for (int o = 1; o < 32; o <<= 1) {
        int y = __shfl_up_sync(0xFFFFFFFFu, x, o);
        if (lane >= o) x += y;
    }
    if (lane == 31) wsum[wid] = x;
    __syncthreads();
    if (wid == 0) {
        int y = (lane < 16) ? wsum[lane] : 0;
        #pragma unroll
        for (int o = 1; o < 16; o <<= 1) {
            int z = __shfl_up_sync(0xFFFFFFFFu, y, o);
            if (lane >= o) y += z;
        }
        if (lane < 16) wsum[lane] = y;
    }
    __syncthreads();
    int base = wid ? wsum[wid - 1] : 0;
    if (g < n2) g_rptr[g] = base + x - v;          // local exclusive prefix
    if (t == 511) g_bsum[blockIdx.x] = base + x;   // block total
}

// scan the block partials (nb <= 256); writes g_rptr[n2] = grand total
__global__ __launch_bounds__(256) void k_s2(int nb, int n2) {
    __shared__ int wsum[8];
    int t = threadIdx.x, lane = t & 31, wid = t >> 5;
    int v = (t < nb) ? g_bsum[t] : 0;
    int x = v;
    #pragma unroll
    for (int o = 1; o < 32; o <<= 1) {
        int y = __shfl_up_sync(0xFFFFFFFFu, x, o);
        if (lane >= o) x += y;
    }
    if (lane == 31) wsum[wid] = x;
    __syncthreads();
    if (wid == 0) {
        int y = (lane < 8) ? wsum[lane] : 0;
        #pragma unroll
        for (int o = 1; o < 8; o <<= 1) {
            int z = __shfl_up_sync(0xFFFFFFFFu, y, o);
            if (lane >= o) y += z;
        }
        if (lane < 8) wsum[lane] = y;
    }
    __syncthreads();
    int base = wid ? wsum[wid - 1] : 0;
    int excl = base + x - v;
    if (t < nb) g_boff[t] = excl;
    if (t == nb - 1) g_rptr[n2] = excl + v;
}

// finalize rptr (+block offset), place self loop, init scatter cursor.
// Also zero the pooling accumulators (consumed much later by k_gate1/2).
__global__ void k_s3(int n2) {
    int t = blockIdx.x * blockDim.x + threadIdx.x;
    if (t < 2) g_sum[t] = 0.0f;
    if (t < DIM) { g_vec[0][t] = 0.0f; g_vec[1][t] = 0.0f; }
    if (t >= n2) return;
    int r = g_rptr[t] + g_boff[t >> 9];
    g_rptr[t] = r;
    g_csrc[r] = t;
    g_cur[t] = r + 1;
}

__global__ void k_scatter(const int* __restrict__ ei1, const int* __restrict__ ei2,
                          int E, int n) {
    int t = blockIdx.x * blockDim.x + threadIdx.x;
    if (t >= 2 * E) return;
    int src, dst;
    if (t < E) { src = ei1[t];            dst = ei1[E + t]; }
    else       { src = ei2[t - E] + n;    dst = ei2[E + (t - E)] + n; }
    int pos = atomicAdd(&g_cur[dst], 1);
    g_csrc[pos] = src;
}

// ---------------- h = x @ W[l]  (+ fused alpha dot-products) ----------------
// 256 threads, 64-row x 128-col tile, 4x8 register tile per thread.
extern __shared__ float s_mm[];
__global__ __launch_bounds__(256) void k_mm(const float* __restrict__ W,
                                            const float* __restrict__ att_s,
                                            const float* __restrict__ att_d,
                                            int l, int n2) {
    float* Ws = s_mm;                    // [128][128]
    float* Xs = s_mm + 16384;            // [64][132] padded
    int tid = threadIdx.x;
    float4* Ws4 = (float4*)Ws;
    const float4* Wg4 = (const float4*)(W + l * DIM * DIM);
    #pragma unroll
    for (int i = 0; i < 16; i++) Ws4[tid + 256 * i] = Wg4[tid + 256 * i];

    int row0 = blockIdx.x * 64;
    #pragma unroll
    for (int i = 0; i < 8; i++) {
        int idx = tid + 256 * i;         // f4 index: row = idx>>5, k4 = idx&31
        int r = idx >> 5, k4 = idx & 31;
        float4 v = make_float4(0.f, 0.f, 0.f, 0.f);
        if (row0 + r < n2) v = ((const float4*)g_x)[(row0 + r) * 32 + k4];
        float* d = Xs + r * 132 + k4 * 4;
        d[0] = v.x; d[1] = v.y; d[2] = v.z; d[3] = v.w;
    }
    __syncthreads();

    int cg = tid & 15, rg = tid >> 4;    // colgroup (8 cols), rowgroup (4 rows)
    float acc[4][8];
    #pragma unroll
    for (int i = 0; i < 4; i++)
        #pragma unroll
        for (int j = 0; j < 8; j++) acc[i][j] = 0.f;

    const float* xs0 = Xs + (rg * 4) * 132;
    #pragma unroll 4
    for (int k = 0; k < DIM; k++) {
        float4 w0 = Ws4[k * 32 + cg * 2];
        float4 w1 = Ws4[k * 32 + cg * 2 + 1];
        float wv[8] = {w0.x, w0.y, w0.z, w0.w, w1.x, w1.y, w1.z, w1.w};
        float xv[4] = {xs0[k], xs0[132 + k], xs0[264 + k], xs0[396 + k]};
        #pragma unroll
        for (int i = 0; i < 4; i++)
            #pragma unroll
            for (int j = 0; j < 8; j++)
                acc[i][j] = fmaf(xv[i], wv[j], acc[i][j]);
    }

    const float4* as4 = (const float4*)(att_s + l * DIM);
    const float4* ad4 = (const float4*)(att_d + l * DIM);
    float4 A0 = as4[cg * 2], A1 = as4[cg * 2 + 1];
    float4 D0 = ad4[cg * 2], D1 = ad4[cg * 2 + 1];
    float av[8] = {A0.x, A0.y, A0.z, A0.w, A1.x, A1.y, A1.z, A1.w};
    float dv[8] = {D0.x, D0.y, D0.z, D0.w, D1.x, D1.y, D1.z, D1.w};
    int head = cg >> 2;

    #pragma unroll
    for (int i = 0; i < 4; i++) {
        int row = row0 + rg * 4 + i;
        if (row < n2) {
            float4 h0 = make_float4(acc[i][0], acc[i][1], acc[i][2], acc[i][3]);
            float4 h1 = make_float4(acc[i][4], acc[i][5], acc[i][6], acc[i][7]);
            ((float4*)g_h)[row * 32 + cg * 2]     = h0;
            ((float4*)g_h)[row * 32 + cg * 2 + 1] = h1;
        }
        float ps = 0.f, pd = 0.f;
        #pragma unroll
        for (int j = 0; j < 8; j++) {
            ps = fmaf(acc[i][j], av[j], ps);
            pd = fmaf(acc[i][j], dv[j], pd);
        }
        ps += __shfl_xor_sync(0xFFFFFFFFu, ps, 1);
        ps += __shfl_xor_sync(0xFFFFFFFFu, ps, 2);
        pd += __shfl_xor_sync(0xFFFFFFFFu, pd, 1);
        pd += __shfl_xor_sync(0xFFFFFFFFu, pd, 2);
        if ((cg & 3) == 0 && row < n2) {
            g_asrc[row * HEADS + head] = ps;
            g_adst[row * HEADS + head] = pd;
        }
    }
}

// ---------------- per-dst aggregation: two-phase softmax, fused epilogue ----
// 1 warp per dst node; lane owns 4 feature dims (float4), head = lane>>3.
__device__ __forceinline__ float pick(float4 v, int h) {
    return h == 0 ? v.x : h == 1 ? v.y : h == 2 ? v.z : v.w;
}
__global__ __launch_bounds__(256) void k_agg(const float* __restrict__ bias,
                                             int l, int n2) {
    int w = (blockIdx.x * blockDim.x + threadIdx.x) >> 5;
    if (w >= n2) return;
    int lane = threadIdx.x & 31;
    int head = lane >> 3;
    const float4* asrc4 = (const float4*)g_asrc;
    const float4* h4    = (const float4*)g_h;
    float4 ad = ((const float4*)g_adst)[w];
    int beg = g_rptr[w], end = g_rptr[w + 1];

    // phase 1: per-head segment max, lanes parallel over edges
    float m0 = -CUDART_INF_F, m1 = m0, m2 = m0, m3 = m0;
    for (int e = beg + lane; e < end; e += 32) {
        float4 a = __ldg(asrc4 + __ldg(g_csrc + e));
        float v;
        v = a.x + ad.x; v = v > 0.f ? v : NEG * v; m0 = fmaxf(m0, v);
        v = a.y + ad.y; v = v > 0.f ? v : NEG * v; m1 = fmaxf(m1, v);
        v = a.z + ad.z; v = v > 0.f ? v : NEG * v; m2 = fmaxf(m2, v);
        v = a.w + ad.w; v = v > 0.f ? v : NEG * v; m3 = fmaxf(m3, v);
    }
    #pragma unroll
    for (int o = 16; o; o >>= 1) {
        m0 = fmaxf(m0, __shfl_xor_sync(0xFFFFFFFFu, m0, o));
        m1 = fmaxf(m1, __shfl_xor_sync(0xFFFFFFFFu, m1, o));
        m2 = fmaxf(m2, __shfl_xor_sync(0xFFFFFFFFu, m2, o));
        m3 = fmaxf(m3, __shfl_xor_sync(0xFFFFFFFFu, m3, o));
    }
    float mh  = head == 0 ? m0   : head == 1 ? m1   : head == 2 ? m2   : m3;
    float adh = head == 0 ? ad.x : head == 1 ? ad.y : head == 2 ? ad.z : ad.w;

    // phase 2: accumulate exp(v-m) * h[src]; independent FMA chains, unroll 4.
    // Indices + all 4 h-row LDG.128s issued back-to-back (front-batched MLP).
    float ssum = 0.f;
    float4 acc = make_float4(0.f, 0.f, 0.f, 0.f);
    int e = beg;
    for (; e + 4 <= end; e += 4) {
        int i0 = __ldg(g_csrc + e),     i1 = __ldg(g_csrc + e + 1);
        int i2 = __ldg(g_csrc + e + 2), i3 = __ldg(g_csrc + e + 3);
        int p0i = i0 * 32 + lane, p1i = i1 * 32 + lane;
        int p2i = i2 * 32 + lane, p3i = i3 * 32 + lane;
        float4 h0 = __ldg(h4 + p0i), h1 = __ldg(h4 + p1i);
        float4 h2 = __ldg(h4 + p2i), h3 = __ldg(h4 + p3i);
        float a0 = pick(__ldg(asrc4 + i0), head), a1 = pick(__ldg(asrc4 + i1), head);
        float a2 = pick(__ldg(asrc4 + i2), head), a3 = pick(__ldg(asrc4 + i3), head);
        float v0 = a0 + adh; v0 = v0 > 0.f ? v0 : NEG * v0;
        float v1 = a1 + adh; v1 = v1 > 0.f ? v1 : NEG * v1;
        float v2 = a2 + adh; v2 = v2 > 0.f ? v2 : NEG * v2;
        float v3 = a3 + adh; v3 = v3 > 0.f ? v3 : NEG * v3;
        float p0 = __expf(v0 - mh), p1 = __expf(v1 - mh);
        float p2 = __expf(v2 - mh), p3 = __expf(v3 - mh);
        ssum += (p0 + p1) + (p2 + p3);
        acc.x = fmaf(p0, h0.x, fmaf(p1, h1.x, fmaf(p2, h2.x, fmaf(p3, h3.x, acc.x))));
        acc.y = fmaf(p0, h0.y, fmaf(p1, h1.y, fmaf(p2, h2.y, fmaf(p3, h3.y, acc.y))));
        acc.z = fmaf(p0, h0.z, fmaf(p1, h1.z, fmaf(p2, h2.z, fmaf(p3, h3.z, acc.z))));
        acc.w = fmaf(p0, h0.w, fmaf(p1, h1.w, fmaf(p2, h2.w, fmaf(p3, h3.w, acc.w))));
    }
    for (; e < end; e++) {
        int i0 = __ldg(g_csrc + e);
        float4 h0 = __ldg(h4 + i0 * 32 + lane);
        float a0 = pick(__ldg(asrc4 + i0), head);
        float v0 = a0 + adh; v0 = v0 > 0.f ? v0 : NEG * v0;
        float p0 = __expf(v0 - mh);
        ssum += p0;
        acc.x = fmaf(p0, h0.x, acc.x);
        acc.y = fmaf(p0, h0.y, acc.y);
        acc.z = fmaf(p0, h0.z, acc.z);
        acc.w = fmaf(p0, h0.w, acc.w);
    }

    float inv = 1.0f / (ssum + GEPS);
    float4 b = ((const float4*)(bias + l * DIM))[lane];
    float4 o;
    o.x = fmaf(acc.x, inv, b.x); o.x = o.x > 0.f ? o.x : 0.f;
    o.y = fmaf(acc.y, inv, b.y); o.y = o.y > 0.f ? o.y : 0.f;
    o.z = fmaf(acc.z, inv, b.z); o.z = o.z > 0.f ? o.z : 0.f;
    o.w = fmaf(acc.w, inv, b.w); o.w = o.w > 0.f ? o.w : 0.f;
    ((float4*)g_x)[w * 32 + lane] = o;
}

// ---------------- global attention pooling ----------------------------------
__global__ __launch_bounds__(256) void k_gate1(const float* __restrict__ gw,
                                               const float* __restrict__ gb,
                                               int n, int n2) {
    int w = (blockIdx.x * blockDim.x + threadIdx.x) >> 5;
    int lane = threadIdx.x & 31;
    if (w >= n2) return;
    float4 xr = ((const float4*)g_x)[w * 32 + lane];
    float4 gv = ((const float4*)gw)[lane];
    float acc = xr.x * gv.x + xr.y * gv.y + xr.z * gv.z + xr.w * gv.w;
    #pragma unroll
    for (int o = 16; o; o >>= 1) acc += __shfl_xor_sync(0xFFFFFFFFu, acc, o);
    if (lane == 0) {
        float g  = 1.0f / (1.0f + __expf(-(acc + gb[0])));
        float eg = __expf(g);           // softmax shift-invariant; g in (0,1)
        g_expg[w] = eg;
        atomicAdd(&g_sum[w >= n ? 1 : 0], eg);
    }
}
// grid (256, 2): y = graph index
__global__ __launch_bounds__(128) void k_gate2(int n) {
    int d = threadIdx.x, gi = blockIdx.y;
    int base = gi * n;
    float acc = 0.0f;
    for (int i = blockIdx.x; i < n; i += gridDim.x)
        acc = fmaf(g_expg[base + i], g_x[(base + i) * DIM + d], acc);
    atomicAdd(&g_vec[gi][d], acc);
}

// ---------------- head MLP ---------------------------------------------------
__global__ __launch_bounds__(128) void k_final(const float* __restrict__ fc1w,
                                               const float* __restrict__ fc1b,
                                               const float* __restrict__ fc2w,
                                               const float* __restrict__ fc2b,
                                               float* __restrict__ out) {
    __shared__ float gcat[2 * DIM];
    __shared__ float hid[DIM];
    int t = threadIdx.x;
    gcat[t]       = g_vec[0][t] / g_sum[0];
    gcat[DIM + t] = g_vec[1][t] / g_sum[1];
    __syncthreads();
    float acc = fc1b[t];
    #pragma unroll 8
    for (int k = 0; k < 2 * DIM; k++) acc = fmaf(gcat[k], fc1w[k * DIM + t], acc);
    acc = acc > 0.0f ? acc : 0.0f;
    hid[t] = acc * fc2w[t];
    __syncthreads();
    for (int s = 64; s; s >>= 1) {
        if (t < s) hid[t] += hid[t + s];
        __syncthreads();
    }
    if (t == 0) out[0] = hid[0] + fc2b[0];
}

// ---------------- launch ----------------------------------------------------
extern "C" void kernel_launch(void* const* d_in, const int* in_sizes, int n_in,
                              void* d_out, int out_size) {
    const int*   x1      = (const int*)  d_in[0];
    const int*   x2      = (const int*)  d_in[1];
    const int*   ei1     = (const int*)  d_in[2];
    const int*   ei2     = (const int*)  d_in[3];
    const float* embed   = (const float*)d_in[4];
    const float* W       = (const float*)d_in[5];
    const float* att_src = (const float*)d_in[6];
    const float* att_dst = (const float*)d_in[7];
    const float* bias    = (const float*)d_in[8];
    const float* gate_w  = (const float*)d_in[9];
    const float* gate_b  = (const float*)d_in[10];
    const float* fc1_w   = (const float*)d_in[11];
    const float* fc1_b   = (const float*)d_in[12];
    const float* fc2_w   = (const float*)d_in[13];
    const float* fc2_b   = (const float*)d_in[14];
    float* out = (float*)d_out;

    int n  = in_sizes[0];
    int E  = in_sizes[2] / 2;
    int n2 = 2 * n;

    int smem_mm = (16384 + 64 * 132) * 4;         // 97.0 KB
    cudaFuncSetAttribute(k_mm, cudaFuncAttributeMaxDynamicSharedMemorySize,
                         smem_mm);

    int gN256 = (n2 + 255) / 256;
    int gE256 = (2 * E + 255) / 256;
    int gGath = (n2 * 32 + 255) / 256;
    int nb    = (n2 + 511) / 512;
    int gMM   = (n2 + 63) / 64;
    int gWarp = (n2 * 32 + 255) / 256;            // 1 warp per node

    // launch order chosen so launch #5 (ncu -s 5 -c 1) is k_mm (layer 0)
    k_gather <<<gGath, 256>>>(x1, x2, embed, n);       // 0 (also inits deg)
    k_count  <<<gE256, 256>>>(ei1, ei2, E, n);          // 1
    k_s1     <<<nb, 512>>>(n2);                         // 2
    k_s2     <<<1, 256>>>(nb, n2);                      // 3
    k_s3     <<<gN256, 256>>>(n2);                      // 4 (also zeroes pool accum)
    k_mm     <<<gMM, 256, smem_mm>>>(W, att_src, att_dst, 0, n2);  // 5
    k_scatter<<<gE256, 256>>>(ei1, ei2, E, n);          // 6
    k_agg    <<<gWarp, 256>>>(bias, 0, n2);             // 7

    for (int l = 1; l < LAYERS; l++) {
        k_mm <<<gMM, 256, smem_mm>>>(W, att_src, att_dst, l, n2);
        k_agg<<<gWarp, 256>>>(bias, l, n2);
    }
    k_gate1<<<gWarp, 256>>>(gate_w, gate_b, n, n2);
    dim3 g2(256, 2);
    k_gate2<<<g2, 128>>>(n);
    k_final<<<1, 128>>>(fc1_w, fc1_b, fc2_w, fc2_b, out);
}